// round 3
// baseline (speedup 1.0000x reference)
#include <cuda_runtime.h>
#include <math.h>
#include <stdint.h>

#define HW   16384
#define Bn   8
#define HIDn 170
#define XSTR 68      // floats per staged X row (17 x 16B granules -> conflict-free)
#define WSTR 68

// ---------------- scratch (static device memory) ----------------
__device__ float g_bufA[Bn * 64 * HW];
__device__ float g_bufR[Bn * 64 * HW];
__device__ float g_bufX[Bn * 64 * HW];
__device__ float g_bufG[Bn * 64 * HW];
__device__ float g_big1[Bn * 340 * HW];
__device__ float g_big2[Bn * 340 * HW];
__device__ float g_attn[Bn * 8 * 64];
__device__ float g_part[64 * 8 * 80];

__device__ __forceinline__ float gelu_f(float x) {
    return 0.5f * x * (1.0f + erff(x * 0.70710678118654752f));
}
__device__ __forceinline__ uint32_t f2tf32(float x) {
    uint32_t r; asm("cvt.rna.tf32.f32 %0, %1;" : "=r"(r) : "f"(x)); return r;
}
__device__ __forceinline__ void ldsm4(uint32_t* a, uint32_t addr) {
    asm volatile("ldmatrix.sync.aligned.m8n8.x4.shared.b16 {%0,%1,%2,%3}, [%4];"
        : "=r"(a[0]), "=r"(a[1]), "=r"(a[2]), "=r"(a[3]) : "r"(addr));
}
__device__ __forceinline__ void mma_tf32(float* d, const uint32_t* a, uint32_t b0, uint32_t b1) {
    asm volatile("mma.sync.aligned.m16n8k8.row.col.f32.tf32.tf32.f32 "
        "{%0,%1,%2,%3}, {%4,%5,%6,%7}, {%8,%9}, {%0,%1,%2,%3};"
        : "+f"(d[0]), "+f"(d[1]), "+f"(d[2]), "+f"(d[3])
        : "r"(a[0]), "r"(a[1]), "r"(a[2]), "r"(a[3]), "r"(b0), "r"(b1));
}

// =================================================================
// Unified tensor-core 1x1 conv: out = W @ f(in) (+resid), LN folded.
//   useln: y = rs[p]*(W~@x - mu[p]*Sg[o]) + Sb[o], W~ = W*gamma
//   gated: x_c = gelu(in_c) * in_{c+170}
//   shift: circular roll folded into input pixel index
// tile: 256 px x 64 out, 256 thr (8 warps), warp = 32px x 64out
// weights split hi/lo tf32 (2-term), activations single tf32
// =================================================================
__global__ void __launch_bounds__(256, 2)
convtc_kernel(const float* __restrict__ in, const float* __restrict__ addp,
              const float* __restrict__ lnw, const float* __restrict__ lnb,
              const float* __restrict__ wt, float* __restrict__ out,
              const float* __restrict__ resid,
              int Cin, int inCh, int Cout, int shift, int useln, int gated)
{
    extern __shared__ float sm[];
    float* Xh   = sm;                       // [256][68]
    float* BF   = sm + 256 * XSTR;          // [8 kb][8 n8][32 lane] float4
    float* mu_s = BF + 8192;                // [256]
    float* rs_s = mu_s + 256;               // [256]
    float* sg_s = rs_s + 256;               // [64]
    float* sb_s = sg_s + 64;                // [64]

    int b = blockIdx.z, p0 = blockIdx.x * 256, o0 = blockIdx.y * 64;
    int tid = threadIdx.x;
    int warp = tid >> 5, lane = tid & 31;

    // this thread's staging pixel
    int p = p0 + tid;
    int ip = p;
    if (shift) {
        int hh = ((p >> 7) + shift) & 127, ww = ((p & 127) + shift) & 127;
        ip = (hh << 7) | ww;
    }
    const float* inb = in + (size_t)b * inCh * HW;
    const float* adb = addp ? addp + (size_t)b * 64 * HW : nullptr;

    float accD[2][8][4];
    #pragma unroll
    for (int t = 0; t < 2; t++)
        #pragma unroll
        for (int n = 0; n < 8; n++)
            #pragma unroll
            for (int q = 0; q < 4; q++) accD[t][n][q] = 0.f;

    int nchunk = (Cin + 63) >> 6;
    for (int ch = 0; ch < nchunk; ch++) {
        if (ch) __syncthreads();
        int c0 = ch << 6;
        // ---- stage X (one row per thread) + inline LN stats ----
        float s_sum = 0.f, s_sq = 0.f;
        #pragma unroll 4
        for (int j4 = 0; j4 < 16; j4++) {
            float v4[4];
            #pragma unroll
            for (int jj = 0; jj < 4; jj++) {
                int c = c0 + j4 * 4 + jj;
                float v = 0.f;
                if (c < Cin) {
                    if (gated) {
                        float a = inb[(size_t)c * HW + ip];
                        float g = inb[(size_t)(c + HIDn) * HW + ip];
                        v = gelu_f(a) * g;
                    } else {
                        v = inb[(size_t)c * HW + ip];
                        if (adb) v += adb[(size_t)c * HW + ip];
                    }
                }
                if (useln) { s_sum += v; s_sq += v * v; }
                v4[jj] = __uint_as_float(f2tf32(v));
            }
            *(float4*)&Xh[tid * XSTR + j4 * 4] = make_float4(v4[0], v4[1], v4[2], v4[3]);
        }
        // ---- stage BF (pre-packed B fragments, hi/lo split) ----
        #pragma unroll
        for (int i = 0; i < 16; i++) {
            int e = i * 256 + tid;
            int o = e >> 6, k = e & 63;
            int og = o0 + o, kg = c0 + k;
            float wv = 0.f;
            if (og < Cout && kg < Cin) wv = wt[(size_t)og * Cin + kg];
            if (useln) wv *= lnw[kg];
            uint32_t whb = f2tf32(wv);
            float wlo = wv - __uint_as_float(whb);
            uint32_t wlb = f2tf32(wlo);
            int kb = k >> 3, kw = k & 7, n8 = o >> 3, nn = o & 7;
            int bl = nn * 4 + (kw & 3);
            int slot = kw >> 2;
            float* dst = &BF[((kb * 8 + n8) * 32 + bl) * 4];
            dst[slot]     = __uint_as_float(whb);
            dst[slot + 2] = __uint_as_float(wlb);
        }
        if (ch == 0) {
            if (useln) {
                float m = s_sum * 0.015625f;
                float var = s_sq * 0.015625f - m * m;
                mu_s[tid] = m;
                rs_s[tid] = rsqrtf(fmaxf(var, 0.f) + 1e-5f);
            }
            if (tid < 64) {
                float sg = 0.f, sb = 0.f;
                if (useln && (o0 + tid) < Cout) {
                    const float* wr = wt + (size_t)(o0 + tid) * Cin;
                    #pragma unroll 8
                    for (int k = 0; k < 64; k++) { sg += wr[k] * lnw[k]; sb += wr[k] * lnb[k]; }
                }
                sg_s[tid] = sg; sb_s[tid] = sb;
            }
        }
        __syncthreads();

        // ---- tensor GEMM over 8 k-blocks ----
        uint32_t xbase = (uint32_t)__cvta_generic_to_shared(Xh);
        int r = lane & 7, madd8 = (lane >> 3) & 1, gsel = lane >> 4;
        uint32_t a_off0 = xbase + (((warp * 32) + r + madd8 * 8) * XSTR + gsel * 4) * 4;
        #pragma unroll
        for (int kb = 0; kb < 8; kb++) {
            uint32_t A0[4], A1[4];
            uint32_t addr0 = a_off0 + kb * 32;          // +8 floats per kb
            ldsm4(A0, addr0);
            ldsm4(A1, addr0 + 16 * XSTR * 4);
            const float4* bfk = (const float4*)&BF[(kb * 8) * 32 * 4];
            #pragma unroll
            for (int n8 = 0; n8 < 8; n8++) {
                float4 bv = bfk[n8 * 32 + lane];
                uint32_t bh0 = __float_as_uint(bv.x), bh1 = __float_as_uint(bv.y);
                uint32_t bl0 = __float_as_uint(bv.z), bl1 = __float_as_uint(bv.w);
                mma_tf32(accD[0][n8], A0, bh0, bh1);
                mma_tf32(accD[0][n8], A0, bl0, bl1);
                mma_tf32(accD[1][n8], A1, bh0, bh1);
                mma_tf32(accD[1][n8], A1, bl0, bl1);
            }
        }
    }

    // ---- epilogue ----
    int gq = lane >> 2, oq = (lane & 3) * 2;
    #pragma unroll
    for (int t = 0; t < 2; t++) {
        int pxa = warp * 32 + t * 16 + gq;
        int pxb = pxa + 8;
        float mua = 0.f, rsa_ = 0.f, mub = 0.f, rsb = 0.f;
        if (useln) { mua = mu_s[pxa]; rsa_ = rs_s[pxa]; mub = mu_s[pxb]; rsb = rs_s[pxb]; }
        #pragma unroll
        for (int n8 = 0; n8 < 8; n8++) {
            #pragma unroll
            for (int q = 0; q < 2; q++) {
                int ol = n8 * 8 + oq + q;
                int og = o0 + ol;
                if (og < Cout) {
                    float v0 = accD[t][n8][q];
                    float v1 = accD[t][n8][q + 2];
                    if (useln) {
                        float sg = sg_s[ol], sb = sb_s[ol];
                        v0 = rsa_ * (v0 - mua * sg) + sb;
                        v1 = rsb * (v1 - mub * sg) + sb;
                    }
                    if (resid) {
                        v0 += resid[((size_t)b * 64 + og) * HW + p0 + pxa];
                        v1 += resid[((size_t)b * 64 + og) * HW + p0 + pxb];
                    }
                    size_t obase = ((size_t)b * Cout + og) * HW + p0;
                    out[obase + pxa] = v0;
                    out[obase + pxb] = v1;
                }
            }
        }
    }
}

// ---------------- depthwise 3x3 conv, zero padding, 4 px/thread ----------------
__global__ void dwconv_kernel(const float* __restrict__ in, const float* __restrict__ wt,
                              float* __restrict__ out, int Ch)
{
    int c = blockIdx.y, b = blockIdx.z;
    int p = (blockIdx.x * 256 + threadIdx.x) << 2;
    int h = p >> 7, w0 = p & 127;
    const float* ib = in + ((size_t)b * Ch + c) * HW;
    const float* wc = wt + c * 9;
    float acc[4] = {0.f, 0.f, 0.f, 0.f};
    #pragma unroll
    for (int dy = -1; dy <= 1; dy++) {
        int hh = h + dy;
        if ((unsigned)hh > 127u) continue;
        const float* row = ib + (hh << 7);
        float4 mid = *(const float4*)(row + w0);
        float r0 = (w0 > 0)   ? row[w0 - 1] : 0.f;
        float r5 = (w0 < 124) ? row[w0 + 4] : 0.f;
        float r[6] = {r0, mid.x, mid.y, mid.z, mid.w, r5};
        float wa = wc[(dy + 1) * 3 + 0], wb = wc[(dy + 1) * 3 + 1], wcc = wc[(dy + 1) * 3 + 2];
        #pragma unroll
        for (int j = 0; j < 4; j++)
            acc[j] += wa * r[j] + wb * r[j + 1] + wcc * r[j + 2];
    }
    *(float4*)(out + ((size_t)b * Ch + c) * HW + p) = make_float4(acc[0], acc[1], acc[2], acc[3]);
}

// =================================================================
// RSA window attention, one 8x8 window (64 px x 64 ch) per block
// =================================================================
__global__ void __launch_bounds__(256, 4)
rsa_attn_kernel(const float* __restrict__ qkv, float* __restrict__ out,
                const float* __restrict__ temp)
{
    extern __shared__ float sm[];
    float* A   = sm;
    float* B   = sm + 64 * WSTR;
    float* C   = sm + 2 * 64 * WSTR;
    float* inv = sm + 3 * 64 * WSTR;
    int blk = blockIdx.x;
    int b = blk >> 8, win = blk & 255;
    int wy = win >> 4, wx = win & 15;
    int tid = threadIdx.x;
    size_t qbase = (size_t)b * 192 * HW;

    for (int e = tid; e < 4096; e += 256) {
        int p = e & 63, c = e >> 6;
        int gp = (((wy << 3) + (p >> 3)) << 7) | ((wx << 3) + (p & 7));
        A[p * WSTR + c] = qkv[qbase + c * HW + gp];
        B[p * WSTR + c] = qkv[qbase + (64 + c) * HW + gp];
    }
    __syncthreads();
    if (tid < 64) {
        int p = tid;
        float nq = 0.f, nk = 0.f;
        #pragma unroll
        for (int c = 0; c < 64; c++) {
            float a = A[p * WSTR + c]; nq += a * a;
            float bb = B[p * WSTR + c]; nk += bb * bb;
        }
        inv[p] = 1.0f / (fmaxf(sqrtf(nq), 1e-12f) * fmaxf(sqrtf(nk), 1e-12f));
    }
    __syncthreads();
    for (int e4 = tid; e4 < 1024; e4 += 256) {
        int p = e4 >> 4, c4 = e4 & 15;
        float iv = inv[p];
        float4 v = ((float4*)B)[p * (WSTR / 4) + c4];
        v.x *= iv; v.y *= iv; v.z *= iv; v.w *= iv;
        ((float4*)B)[p * (WSTR / 4) + c4] = v;
    }
    __syncthreads();
    float tscale = temp[0];
    {
        int c0 = (tid >> 4) << 2, d0 = (tid & 15) << 2;
        float s[4][4] = {};
        #pragma unroll 4
        for (int p = 0; p < 64; p++) {
            float4 qv = *(const float4*)(A + p * WSTR + c0);
            float4 kv = *(const float4*)(B + p * WSTR + d0);
            float qr[4] = {qv.x, qv.y, qv.z, qv.w};
            float kr[4] = {kv.x, kv.y, kv.z, kv.w};
            #pragma unroll
            for (int i = 0; i < 4; i++)
                #pragma unroll
                for (int j = 0; j < 4; j++) s[i][j] += qr[i] * kr[j];
        }
        #pragma unroll
        for (int i = 0; i < 4; i++)
            *(float4*)(C + (c0 + i) * WSTR + d0) =
                make_float4(fmaxf(0.f, tscale * s[i][0]), fmaxf(0.f, tscale * s[i][1]),
                            fmaxf(0.f, tscale * s[i][2]), fmaxf(0.f, tscale * s[i][3]));
    }
    __syncthreads();
    for (int e = tid; e < 4096; e += 256) {
        int p = e & 63, c = e >> 6;
        int gp = (((wy << 3) + (p >> 3)) << 7) | ((wx << 3) + (p & 7));
        A[c * WSTR + p] = qkv[qbase + (128 + c) * HW + gp];
    }
    __syncthreads();
    {
        int p0 = (tid >> 4) << 2, d0 = (tid & 15) << 2;
        float s[4][4] = {};
        #pragma unroll 4
        for (int c = 0; c < 64; c++) {
            float4 vv = *(const float4*)(A + c * WSTR + p0);
            float4 av = *(const float4*)(C + c * WSTR + d0);
            float vr[4] = {vv.x, vv.y, vv.z, vv.w};
            float ar[4] = {av.x, av.y, av.z, av.w};
            #pragma unroll
            for (int i = 0; i < 4; i++)
                #pragma unroll
                for (int j = 0; j < 4; j++) s[i][j] += vr[i] * ar[j];
        }
        #pragma unroll
        for (int j = 0; j < 4; j++)
            *(float4*)(B + (d0 + j) * WSTR + p0) = make_float4(s[0][j], s[1][j], s[2][j], s[3][j]);
    }
    __syncthreads();
    size_t obase = (size_t)b * 64 * HW;
    for (int e = tid; e < 4096; e += 256) {
        int p = e & 63, d = e >> 6;
        int gp = (((wy << 3) + (p >> 3)) << 7) | ((wx << 3) + (p & 7));
        out[obase + d * HW + gp] = B[d * WSTR + p];
    }
}

// ---------------- GSA: partial Gram sums (chunked) -------------------------------
__global__ void gsa_attn_part(const float* __restrict__ qkv, float* __restrict__ part)
{
    __shared__ float red[8][80];
    int bh = blockIdx.y;
    int b = bh >> 3, hd = bh & 7;
    int chunk = blockIdx.x;
    int tid = threadIdx.x;
    const float* qb = qkv + ((size_t)b * 192 + hd * 8) * HW;
    const float* kb = qkv + ((size_t)b * 192 + 64 + hd * 8) * HW;
    float dot[8][8] = {};
    float qn[8] = {}, kn[8] = {};
    int n0 = chunk * 2048;
    for (int n = n0 + tid; n < n0 + 2048; n += 256) {
        float qv[8], kv[8];
        #pragma unroll
        for (int i = 0; i < 8; i++) { qv[i] = qb[i * HW + n]; kv[i] = kb[i * HW + n]; }
        #pragma unroll
        for (int i = 0; i < 8; i++) { qn[i] += qv[i] * qv[i]; kn[i] += kv[i] * kv[i]; }
        #pragma unroll
        for (int i = 0; i < 8; i++)
            #pragma unroll
            for (int j = 0; j < 8; j++) dot[i][j] += qv[i] * kv[j];
    }
    int lane = tid & 31, w = tid >> 5;
    #pragma unroll
    for (int i = 0; i < 8; i++)
        #pragma unroll
        for (int j = 0; j < 8; j++) {
            float v = dot[i][j];
            #pragma unroll
            for (int off = 16; off; off >>= 1) v += __shfl_xor_sync(0xffffffffu, v, off);
            if (lane == 0) red[w][i * 8 + j] = v;
        }
    #pragma unroll
    for (int i = 0; i < 8; i++) {
        float v = qn[i];
        #pragma unroll
        for (int off = 16; off; off >>= 1) v += __shfl_xor_sync(0xffffffffu, v, off);
        if (lane == 0) red[w][64 + i] = v;
        float u = kn[i];
        #pragma unroll
        for (int off = 16; off; off >>= 1) u += __shfl_xor_sync(0xffffffffu, u, off);
        if (lane == 0) red[w][72 + i] = u;
    }
    __syncthreads();
    if (tid < 80) {
        float s = 0.f;
        #pragma unroll
        for (int w2 = 0; w2 < 8; w2++) s += red[w2][tid];
        part[((size_t)bh * 8 + chunk) * 80 + tid] = s;
    }
}

__global__ void gsa_attn_final(const float* __restrict__ part, float* __restrict__ attn,
                               const float* __restrict__ temp)
{
    __shared__ float fin[80];
    int bh = blockIdx.x, tid = threadIdx.x;
    if (tid < 80) {
        float s = 0.f;
        #pragma unroll
        for (int c = 0; c < 8; c++) s += part[((size_t)bh * 8 + c) * 80 + tid];
        fin[tid] = s;
    }
    __syncthreads();
    if (tid < 64) {
        int c = tid >> 3, d = tid & 7;
        float nq = fmaxf(sqrtf(fin[64 + c]), 1e-12f);
        float nk = fmaxf(sqrtf(fin[72 + d]), 1e-12f);
        attn[(size_t)bh * 64 + tid] = fmaxf(0.f, temp[0] * fin[tid] / (nq * nk));
    }
}

// ---------------- GSA: apply attention, (head,c)->(c*8+head) reorder -------------
__global__ void gsa_apply_kernel(const float* __restrict__ qkv, const float* __restrict__ attn,
                                 float* __restrict__ out)
{
    __shared__ float at[512];
    int b = blockIdx.y;
    int tid = threadIdx.x;
    for (int e = tid; e < 512; e += 256) at[e] = attn[b * 512 + e];
    __syncthreads();
    int n = blockIdx.x * 256 + tid;
    const float* vb = qkv + ((size_t)b * 192 + 128) * HW + n;
    float* ob = out + (size_t)b * 64 * HW + n;
    #pragma unroll
    for (int hd = 0; hd < 8; hd++) {
        float vv[8];
        #pragma unroll
        for (int d = 0; d < 8; d++) vv[d] = vb[(hd * 8 + d) * HW];
        #pragma unroll
        for (int cc = 0; cc < 8; cc++) {
            float s = 0.f;
            #pragma unroll
            for (int d = 0; d < 8; d++) s += at[hd * 64 + cc * 8 + d] * vv[d];
            ob[(cc * 8 + hd) * HW] = s;
        }
    }
}

// ---------------- launch ---------------------------------------------------------
extern "C" void kernel_launch(void* const* d_in, const int* in_sizes, int n_in,
                              void* d_out, int out_size)
{
    const float* x         = (const float*)d_in[0];
    const float* ln_s0_w   = (const float*)d_in[1];
    const float* ln_s0_b   = (const float*)d_in[2];
    const float* ln_s2_w   = (const float*)d_in[3];
    const float* ln_s2_b   = (const float*)d_in[4];
    const float* rsa_qkv_w = (const float*)d_in[5];
    const float* rsa_dw_w  = (const float*)d_in[6];
    const float* rsa_proj_w= (const float*)d_in[7];
    const float* rsa_temp  = (const float*)d_in[8];
    const float* ffs_in_w  = (const float*)d_in[9];
    const float* ffs_dw_w  = (const float*)d_in[10];
    const float* ffs_out_w = (const float*)d_in[11];
    const float* ln_c0_w   = (const float*)d_in[12];
    const float* ln_c0_b   = (const float*)d_in[13];
    const float* ln_c2_w   = (const float*)d_in[14];
    const float* ln_c2_b   = (const float*)d_in[15];
    const float* gsa_qkv_w = (const float*)d_in[16];
    const float* gsa_dw_w  = (const float*)d_in[17];
    const float* gsa_proj_w= (const float*)d_in[18];
    const float* gsa_temp  = (const float*)d_in[19];
    const float* ffc_in_w  = (const float*)d_in[20];
    const float* ffc_dw_w  = (const float*)d_in[21];
    const float* ffc_out_w = (const float*)d_in[22];
    float* outp = (float*)d_out;

    float *bufA, *bufR, *bufX, *bufG, *big1, *big2, *attnb, *partb;
    cudaGetSymbolAddress((void**)&bufA,  g_bufA);
    cudaGetSymbolAddress((void**)&bufR,  g_bufR);
    cudaGetSymbolAddress((void**)&bufX,  g_bufX);
    cudaGetSymbolAddress((void**)&bufG,  g_bufG);
    cudaGetSymbolAddress((void**)&big1,  g_big1);
    cudaGetSymbolAddress((void**)&big2,  g_big2);
    cudaGetSymbolAddress((void**)&attnb, g_attn);
    cudaGetSymbolAddress((void**)&partb, g_part);

    const int ctc_smem = (256 * XSTR + 8192 + 256 + 256 + 64 + 64) * (int)sizeof(float); // 104960
    const int rsa_smem = (3 * 64 * WSTR + 64) * (int)sizeof(float);
    cudaFuncSetAttribute(convtc_kernel, cudaFuncAttributeMaxDynamicSharedMemorySize, ctc_smem);
    cudaFuncSetAttribute(rsa_attn_kernel, cudaFuncAttributeMaxDynamicSharedMemorySize, rsa_smem);

    // ---- stage 1: RSA + spatial FFN ----
    convtc_kernel<<<dim3(64, 3, Bn), 256, ctc_smem>>>(x, nullptr, ln_s0_w, ln_s0_b, rsa_qkv_w, big1, nullptr, 64, 64, 192,  4, 1, 0);
    dwconv_kernel<<<dim3(16, 192, Bn), 256>>>(big1, rsa_dw_w, big2, 192);
    rsa_attn_kernel<<<Bn * 256, 256, rsa_smem>>>(big2, bufA, rsa_temp);
    convtc_kernel<<<dim3(64, 1, Bn), 256, ctc_smem>>>(bufA, nullptr, nullptr, nullptr, rsa_proj_w, bufR, nullptr, 64, 64, 64, -4, 0, 0);
    convtc_kernel<<<dim3(64, 6, Bn), 256, ctc_smem>>>(bufR, x, ln_s2_w, ln_s2_b, ffs_in_w, big1, nullptr, 64, 64, 340, 0, 1, 0);
    dwconv_kernel<<<dim3(16, 340, Bn), 256>>>(big1, ffs_dw_w, big2, 340);
    convtc_kernel<<<dim3(64, 1, Bn), 256, ctc_smem>>>(big2, nullptr, nullptr, nullptr, ffs_out_w, bufX, bufR, 170, 340, 64, 0, 0, 1);

    // ---- stage 2: GSA + channel FFN ----
    convtc_kernel<<<dim3(64, 3, Bn), 256, ctc_smem>>>(bufX, nullptr, ln_c0_w, ln_c0_b, gsa_qkv_w, big1, nullptr, 64, 64, 192, 0, 1, 0);
    dwconv_kernel<<<dim3(16, 192, Bn), 256>>>(big1, gsa_dw_w, big2, 192);
    gsa_attn_part<<<dim3(8, 64), 256>>>(big2, partb);
    gsa_attn_final<<<64, 128>>>(partb, attnb, gsa_temp);
    gsa_apply_kernel<<<dim3(64, Bn), 256>>>(big2, attnb, bufA);
    convtc_kernel<<<dim3(64, 1, Bn), 256, ctc_smem>>>(bufA, nullptr, nullptr, nullptr, gsa_proj_w, bufG, nullptr, 64, 64, 64, 0, 0, 0);
    convtc_kernel<<<dim3(64, 6, Bn), 256, ctc_smem>>>(bufG, bufX, ln_c2_w, ln_c2_b, ffc_in_w, big1, nullptr, 64, 64, 340, 0, 1, 0);
    dwconv_kernel<<<dim3(16, 340, Bn), 256>>>(big1, ffc_dw_w, big2, 340);
    convtc_kernel<<<dim3(64, 1, Bn), 256, ctc_smem>>>(big2, nullptr, nullptr, nullptr, ffc_out_w, outp, bufG, 170, 340, 64, 0, 0, 1);
}